// round 3
// baseline (speedup 1.0000x reference)
#include <cuda_runtime.h>
#include <math.h>

#define NGEO 1024
#define RROT 1000000
#define EREPN 2000000
#define NGBB (NGEO*4096)
#define ROTLEN (2 + RROT*9)

#define OFF_H     0
#define OFF_DQ    4194304
#define OFF_EREP  4259840
#define OFF_EORB  4260864
#define OFF_RHO   4326400
#define OFF_EELEC 8520704
#define OFF_EREF  8521728

__device__ float g_rot[ROTLEN];
__device__ float g_fockp[NGBB];
__device__ float g_ener2[NGEO];

// ---------------- Kernel 1: rotation stage ----------------
__global__ void k_rot(const float* __restrict__ net, const float* __restrict__ T,
                      const int* __restrict__ gidx) {
    __shared__ float sT[256 * 27];
    const long base = (long)blockIdx.x * 256;
    const long tb = base * 27;
    const long tmax = (long)RROT * 27;
    for (int i = threadIdx.x; i < 256 * 27; i += 256) {
        long gi = tb + i;
        if (gi < tmax) sT[i] = T[gi];
    }
    __syncthreads();
    long r = base + threadIdx.x;
    float o[9];
    if (r < RROT) {
        int ib = 3 * (int)r;
        float v0 = net[gidx[ib]], v1 = net[gidx[ib + 1]], v2 = net[gidx[ib + 2]];
        const float* t = &sT[threadIdx.x * 27];
#pragma unroll
        for (int j = 0; j < 9; j++)
            o[j] = t[3 * j] * v0 + t[3 * j + 1] * v1 + t[3 * j + 2] * v2;
    }
    __syncthreads();
    float* sO = sT;
    if (r < RROT) {
#pragma unroll
        for (int j = 0; j < 9; j++) sO[threadIdx.x * 9 + j] = o[j];
    }
    __syncthreads();
    long ob = 2 + base * 9;
    for (int i = threadIdx.x; i < 256 * 9; i += 256) {
        long gi = ob + i;
        if (gi < (long)ROTLEN) g_rot[gi] = sO[i];
    }
    if (blockIdx.x == 0 && threadIdx.x == 0) { g_rot[0] = 0.0f; g_rot[1] = 1.0f; }
}

// ---------------- Kernel 2: H gather ----------------
__global__ void k_hgather(const int* __restrict__ oper, float* __restrict__ outH) {
    int i = blockIdx.x * blockDim.x + threadIdx.x;
    int4 idx = ((const int4*)oper)[i];
    float4 v;
    v.x = g_rot[idx.x]; v.y = g_rot[idx.y]; v.z = g_rot[idx.z]; v.w = g_rot[idx.w];
    ((float4*)outH)[i] = v;
}

// ---------------- Kernel 3: dQ, ep, ener2, F, fockp ----------------
__global__ void k_pre(const float* __restrict__ S, const float* __restrict__ G,
                      const float* __restrict__ rho, const float* __restrict__ qn,
                      const float* __restrict__ phiS, const float* __restrict__ H,
                      float* __restrict__ out_dQ) {
    extern __shared__ float sm[];
    float* b1 = sm;          // S, then T1
    float* b2 = sm + 4160;   // F
    float* b3 = sm + 8320;   // phiS
    __shared__ float sdQ[64], sep[64];
    int g = blockIdx.x, tid = threadIdx.x;
    const float* Sg = S + (size_t)g * 4096;
    const float* Gg = G + (size_t)g * 4096;
    const float* Rg = rho + (size_t)g * 4096;
    const float* Pg = phiS + (size_t)g * 4096;
    const float* Hg = H + (size_t)g * 4096;

    for (int i = tid; i < 4096; i += 256) {
        int r = i >> 6, c = i & 63;
        b1[r * 65 + c] = Sg[i];
        b3[r * 65 + c] = Pg[i];
    }
    __syncthreads();
    int w = tid >> 5, lane = tid & 31;
    for (int rr = 0; rr < 8; rr++) {
        int row = w * 8 + rr;
        float x = Rg[row * 64 + lane] * b1[row * 65 + lane]
                + Rg[row * 64 + lane + 32] * b1[row * 65 + lane + 32];
        for (int o = 16; o; o >>= 1) x += __shfl_xor_sync(0xffffffffu, x, o);
        if (!lane) sdQ[row] = qn[g * 64 + row] - x;
    }
    __syncthreads();
    for (int rr = 0; rr < 8; rr++) {
        int row = w * 8 + rr;
        float x = Gg[row * 64 + lane] * sdQ[lane]
                + Gg[row * 64 + lane + 32] * sdQ[lane + 32];
        for (int o = 16; o; o >>= 1) x += __shfl_xor_sync(0xffffffffu, x, o);
        if (!lane) sep[row] = x;
    }
    __syncthreads();
    if (tid < 64) out_dQ[g * 64 + tid] = sdQ[tid];
    if (tid < 32) {
        float e = sdQ[tid] * sep[tid] + sdQ[tid + 32] * sep[tid + 32];
        for (int o = 16; o; o >>= 1) e += __shfl_xor_sync(0xffffffffu, e, o);
        if (!tid) g_ener2[g] = 0.5f * e;
    }
    for (int i = tid; i < 4096; i += 256) {
        int r = i >> 6, c = i & 63;
        b2[r * 65 + c] = Hg[i] - 0.5f * b1[r * 65 + c] * (sep[r] + sep[c]);
    }
    __syncthreads();
    int tx = tid & 15, ty = tid >> 4, r0 = ty * 4, c0 = tx * 4;
    float acc[4][4];
    // T1 = F @ phiS
#pragma unroll
    for (int i = 0; i < 4; i++)
#pragma unroll
        for (int j = 0; j < 4; j++) acc[i][j] = 0.0f;
    for (int k = 0; k < 64; k++) {
        float a0 = b2[(r0 + 0) * 65 + k], a1 = b2[(r0 + 1) * 65 + k];
        float a2 = b2[(r0 + 2) * 65 + k], a3 = b2[(r0 + 3) * 65 + k];
        float q0 = b3[k * 65 + c0], q1 = b3[k * 65 + c0 + 1];
        float q2 = b3[k * 65 + c0 + 2], q3 = b3[k * 65 + c0 + 3];
        acc[0][0] += a0 * q0; acc[0][1] += a0 * q1; acc[0][2] += a0 * q2; acc[0][3] += a0 * q3;
        acc[1][0] += a1 * q0; acc[1][1] += a1 * q1; acc[1][2] += a1 * q2; acc[1][3] += a1 * q3;
        acc[2][0] += a2 * q0; acc[2][1] += a2 * q1; acc[2][2] += a2 * q2; acc[2][3] += a2 * q3;
        acc[3][0] += a3 * q0; acc[3][1] += a3 * q1; acc[3][2] += a3 * q2; acc[3][3] += a3 * q3;
    }
    __syncthreads();   // b1 (S) no longer needed by anyone
#pragma unroll
    for (int i = 0; i < 4; i++)
#pragma unroll
        for (int j = 0; j < 4; j++) b1[(r0 + i) * 65 + c0 + j] = acc[i][j];
    __syncthreads();
    // fockp = phiS^T @ T1
#pragma unroll
    for (int i = 0; i < 4; i++)
#pragma unroll
        for (int j = 0; j < 4; j++) acc[i][j] = 0.0f;
    for (int k = 0; k < 64; k++) {
        float a0 = b3[k * 65 + r0 + 0], a1 = b3[k * 65 + r0 + 1];
        float a2 = b3[k * 65 + r0 + 2], a3 = b3[k * 65 + r0 + 3];
        float q0 = b1[k * 65 + c0], q1 = b1[k * 65 + c0 + 1];
        float q2 = b1[k * 65 + c0 + 2], q3 = b1[k * 65 + c0 + 3];
        acc[0][0] += a0 * q0; acc[0][1] += a0 * q1; acc[0][2] += a0 * q2; acc[0][3] += a0 * q3;
        acc[1][0] += a1 * q0; acc[1][1] += a1 * q1; acc[1][2] += a1 * q2; acc[1][3] += a1 * q3;
        acc[2][0] += a2 * q0; acc[2][1] += a2 * q1; acc[2][2] += a2 * q2; acc[2][3] += a2 * q3;
        acc[3][0] += a3 * q0; acc[3][1] += a3 * q1; acc[3][2] += a3 * q2; acc[3][3] += a3 * q3;
    }
    float* fo = g_fockp + (size_t)g * 4096;
#pragma unroll
    for (int i = 0; i < 4; i++)
#pragma unroll
        for (int j = 0; j < 4; j++) fo[(r0 + i) * 64 + c0 + j] = acc[i][j];
}

// ---------------- Kernel 4: Erep (binary search per segment) ----------------
__global__ void k_erep(const float* __restrict__ net, const int* __restrict__ gr,
                       const int* __restrict__ seg, float* __restrict__ out_erep) {
    __shared__ int sbnd[2];
    __shared__ float sred[256];
    int g = blockIdx.x, tid = threadIdx.x;
    if (tid < 2) {
        int target = g + tid, lo = 0, hi = EREPN;
        while (lo < hi) {
            int mid = (lo + hi) >> 1;
            if (seg[mid] < target) lo = mid + 1; else hi = mid;
        }
        sbnd[tid] = lo;
    }
    __syncthreads();
    float s = 0.0f;
    for (int i = sbnd[0] + tid; i < sbnd[1]; i += 256) s += net[gr[i]];
    sred[tid] = s;
    __syncthreads();
    for (int o = 128; o; o >>= 1) {
        if (tid < o) sred[tid] += sred[tid + o];
        __syncthreads();
    }
    if (!tid) out_erep[g] = sred[0];
}

// ---------------- Kernel 5: Jacobi eigensolver + post-eig ----------------
__global__ void k_eig(const float* __restrict__ phiS, const float* __restrict__ occ,
                      const float* __restrict__ outH, float* __restrict__ out) {
    extern __shared__ float sm[];
    float* b1 = sm;          // A, later orb_filled
    float* b2 = sm + 4160;   // V
    float* b3 = sm + 8320;   // phiS
    __shared__ float sd[64], sc[32], ss[32], sred[256], sfrob;
    __shared__ int sp[32], sq[32], scol[64], sflag;
    int g = blockIdx.x, tid = threadIdx.x;
    const float* fp = g_fockp + (size_t)g * 4096;
    const float* Pg = phiS + (size_t)g * 4096;

    float fl = 0.0f;
    for (int i = tid; i < 4096; i += 256) {
        int r = i >> 6, c = i & 63;
        float v = 0.5f * (fp[i] + fp[c * 64 + r]);   // jax eigh symmetrizes
        b1[r * 65 + c] = v;
        fl += v * v;
        b2[r * 65 + c] = (r == c) ? 1.0f : 0.0f;
        b3[r * 65 + c] = Pg[i];
    }
    sred[tid] = fl;
    __syncthreads();
    for (int o = 128; o; o >>= 1) {
        if (tid < o) sred[tid] += sred[tid + o];
        __syncthreads();
    }
    if (!tid) { sfrob = sred[0]; sflag = 0; }
    __syncthreads();

    for (int sweep = 0; sweep < 16; sweep++) {
        for (int rnd = 0; rnd < 63; rnd++) {
            if (tid < 32) {
                int k = tid, p, q;
                if (k == 0) { p = 63; q = rnd % 63; }
                else { p = (rnd + k) % 63; q = (rnd + 63 - k) % 63; }
                if (p > q) { int t = p; p = q; q = t; }
                sp[k] = p; sq[k] = q;
                float app = b1[p * 65 + p], aqq = b1[q * 65 + q], apq = b1[p * 65 + q];
                float c, s;
                if (fabsf(apq) < 1e-30f) { c = 1.0f; s = 0.0f; }
                else {
                    float tau = (aqq - app) / (2.0f * apq);
                    float t = copysignf(1.0f / (fabsf(tau) + sqrtf(1.0f + tau * tau)), tau);
                    c = rsqrtf(1.0f + t * t);
                    s = t * c;
                }
                sc[k] = c; ss[k] = s;
            }
            __syncthreads();
#pragma unroll
            for (int it = 0; it < 4; it++) {
                int m = tid + it * 256;
                int I = m >> 5, J = m & 31;
                int pI = sp[I], qI = sq[I], pJ = sp[J], qJ = sq[J];
                float cI = sc[I], sI = ss[I], cJ = sc[J], sJ = ss[J];
                float a00 = b1[pI * 65 + pJ], a01 = b1[pI * 65 + qJ];
                float a10 = b1[qI * 65 + pJ], a11 = b1[qI * 65 + qJ];
                float t00 = cI * a00 - sI * a10, t01 = cI * a01 - sI * a11;
                float t10 = sI * a00 + cI * a10, t11 = sI * a01 + cI * a11;
                b1[pI * 65 + pJ] = cJ * t00 - sJ * t01;
                b1[pI * 65 + qJ] = sJ * t00 + cJ * t01;
                b1[qI * 65 + pJ] = cJ * t10 - sJ * t11;
                b1[qI * 65 + qJ] = sJ * t10 + cJ * t11;
            }
#pragma unroll
            for (int it = 0; it < 8; it++) {
                int m = tid + it * 256;
                int row = m >> 5, k = m & 31;
                int p = sp[k], q = sq[k];
                float c = sc[k], s = ss[k];
                float x = b2[row * 65 + p], y = b2[row * 65 + q];
                b2[row * 65 + p] = c * x - s * y;
                b2[row * 65 + q] = s * x + c * y;
            }
            __syncthreads();
        }
        float off = 0.0f;
        for (int i = tid; i < 4096; i += 256) {
            int r = i >> 6, c = i & 63;
            if (r != c) { float v = b1[r * 65 + c]; off += v * v; }
        }
        sred[tid] = off;
        __syncthreads();
        for (int o = 128; o; o >>= 1) {
            if (tid < o) sred[tid] += sred[tid + o];
            __syncthreads();
        }
        if (!tid && sred[0] <= 1e-11f * sfrob) sflag = 1;
        __syncthreads();
        if (sflag) break;
    }

    // eigenvalue rank sort (ascending, stable)
    if (tid < 64) sd[tid] = b1[tid * 65 + tid];
    __syncthreads();
    if (tid < 64) {
        float d = sd[tid];
        int r = 0;
        for (int j = 0; j < 64; j++)
            r += (sd[j] < d) || (sd[j] == d && j < tid);
        scol[r] = tid;
        out[OFF_EORB + g * 64 + r] = d;
    }
    __syncthreads();

    int tx = tid & 15, ty = tid >> 4, r0 = ty * 4, c0 = tx * 4;
    const float* Og = occ + (size_t)g * 4096;
    const float* Hg = outH + (size_t)g * 4096;
    float acc[4][4];
    // orb_filled = occ * (phiS @ V[:, perm])  -> b1
    int j0 = scol[c0], j1 = scol[c0 + 1], j2 = scol[c0 + 2], j3 = scol[c0 + 3];
#pragma unroll
    for (int i = 0; i < 4; i++)
#pragma unroll
        for (int j = 0; j < 4; j++) acc[i][j] = 0.0f;
    for (int k = 0; k < 64; k++) {
        float a0 = b3[(r0 + 0) * 65 + k], a1 = b3[(r0 + 1) * 65 + k];
        float a2 = b3[(r0 + 2) * 65 + k], a3 = b3[(r0 + 3) * 65 + k];
        float q0 = b2[k * 65 + j0], q1 = b2[k * 65 + j1];
        float q2 = b2[k * 65 + j2], q3 = b2[k * 65 + j3];
        acc[0][0] += a0 * q0; acc[0][1] += a0 * q1; acc[0][2] += a0 * q2; acc[0][3] += a0 * q3;
        acc[1][0] += a1 * q0; acc[1][1] += a1 * q1; acc[1][2] += a1 * q2; acc[1][3] += a1 * q3;
        acc[2][0] += a2 * q0; acc[2][1] += a2 * q1; acc[2][2] += a2 * q2; acc[2][3] += a2 * q3;
        acc[3][0] += a3 * q0; acc[3][1] += a3 * q1; acc[3][2] += a3 * q2; acc[3][3] += a3 * q3;
    }
    __syncthreads();   // all reads of A (diag) done
#pragma unroll
    for (int i = 0; i < 4; i++)
#pragma unroll
        for (int j = 0; j < 4; j++)
            b1[(r0 + i) * 65 + c0 + j] = Og[(r0 + i) * 64 + c0 + j] * acc[i][j];
    __syncthreads();
    // rho_out = 2 * orbf @ orbf^T ; ener1 = sum(rho_out * H)
#pragma unroll
    for (int i = 0; i < 4; i++)
#pragma unroll
        for (int j = 0; j < 4; j++) acc[i][j] = 0.0f;
    for (int k = 0; k < 64; k++) {
        float a0 = b1[(r0 + 0) * 65 + k], a1 = b1[(r0 + 1) * 65 + k];
        float a2 = b1[(r0 + 2) * 65 + k], a3 = b1[(r0 + 3) * 65 + k];
        float q0 = b1[(c0 + 0) * 65 + k], q1 = b1[(c0 + 1) * 65 + k];
        float q2 = b1[(c0 + 2) * 65 + k], q3 = b1[(c0 + 3) * 65 + k];
        acc[0][0] += a0 * q0; acc[0][1] += a0 * q1; acc[0][2] += a0 * q2; acc[0][3] += a0 * q3;
        acc[1][0] += a1 * q0; acc[1][1] += a1 * q1; acc[1][2] += a1 * q2; acc[1][3] += a1 * q3;
        acc[2][0] += a2 * q0; acc[2][1] += a2 * q1; acc[2][2] += a2 * q2; acc[2][3] += a2 * q3;
        acc[3][0] += a3 * q0; acc[3][1] += a3 * q1; acc[3][2] += a3 * q2; acc[3][3] += a3 * q3;
    }
    float* Ro = out + OFF_RHO + (size_t)g * 4096;
    float e1 = 0.0f;
#pragma unroll
    for (int i = 0; i < 4; i++)
#pragma unroll
        for (int j = 0; j < 4; j++) {
            float v = 2.0f * acc[i][j];
            Ro[(r0 + i) * 64 + c0 + j] = v;
            e1 += v * Hg[(r0 + i) * 64 + c0 + j];
        }
    sred[tid] = e1;
    __syncthreads();
    for (int o = 128; o; o >>= 1) {
        if (tid < o) sred[tid] += sred[tid + o];
        __syncthreads();
    }
    if (!tid) out[OFF_EELEC + g] = sred[0] + g_ener2[g];
}

// ---------------- Kernel 6: Eref ----------------
__global__ void k_eref(const float* __restrict__ zc, const float* __restrict__ rv,
                       float* __restrict__ out) {
    if (threadIdx.x == 0) {
        float s = 0.0f;
        for (int i = 0; i < 7; i++) s += zc[i] * rv[i];
        out[OFF_EREF] = s;
    }
}

extern "C" void kernel_launch(void* const* d_in, const int* in_sizes, int n_in,
                              void* d_out, int out_size) {
    const float* net   = (const float*)d_in[0];
    const float* rotT  = (const float*)d_in[1];
    const float* S     = (const float*)d_in[2];
    const float* G     = (const float*)d_in[3];
    const float* rho   = (const float*)d_in[4];
    const float* qn    = (const float*)d_in[5];
    const float* occ   = (const float*)d_in[6];
    const float* phiS  = (const float*)d_in[7];
    const float* zc    = (const float*)d_in[8];
    const float* rv    = (const float*)d_in[9];
    const int* grot    = (const int*)d_in[10];
    const int* goper   = (const int*)d_in[11];
    const int* grep    = (const int*)d_in[12];
    const int* segrep  = (const int*)d_in[13];
    float* out = (float*)d_out;

    static bool attr_done = false;
    if (!attr_done) {
        cudaFuncSetAttribute(k_pre, cudaFuncAttributeMaxDynamicSharedMemorySize, 49920);
        cudaFuncSetAttribute(k_eig, cudaFuncAttributeMaxDynamicSharedMemorySize, 49920);
        attr_done = true;
    }

    k_rot<<<(RROT + 255) / 256, 256>>>(net, rotT, grot);
    k_hgather<<<NGBB / 4 / 256, 256>>>(goper, out + OFF_H);
    k_pre<<<NGEO, 256, 49920>>>(S, G, rho, qn, phiS, out + OFF_H, out + OFF_DQ);
    k_erep<<<NGEO, 256>>>(net, grep, segrep, out + OFF_EREP);
    k_eig<<<NGEO, 256, 49920>>>(phiS, occ, out + OFF_H, out);
    k_eref<<<1, 32>>>(zc, rv, out);
}

// round 4
// speedup vs baseline: 1.3303x; 1.3303x over previous
#include <cuda_runtime.h>
#include <math.h>

#define NGEO 1024
#define RROT 1000000
#define EREPN 2000000
#define NGBB (NGEO*4096)
#define ROTLEN (2 + RROT*9)

#define OFF_H     0
#define OFF_DQ    4194304
#define OFF_EREP  4259840
#define OFF_EORB  4260864
#define OFF_RHO   4326400
#define OFF_EELEC 8520704
#define OFF_EREF  8521728

__device__ float g_rot[ROTLEN];
__device__ float g_fockp[NGBB];
__device__ float g_ener2[NGEO];

// ---------------- Kernel 1: rotation stage ----------------
__global__ void k_rot(const float* __restrict__ net, const float* __restrict__ T,
                      const int* __restrict__ gidx) {
    __shared__ float sT[256 * 27];
    const long base = (long)blockIdx.x * 256;
    const long tb = base * 27;
    const long tmax = (long)RROT * 27;
    for (int i = threadIdx.x; i < 256 * 27; i += 256) {
        long gi = tb + i;
        if (gi < tmax) sT[i] = T[gi];
    }
    __syncthreads();
    long r = base + threadIdx.x;
    float o[9];
    if (r < RROT) {
        int ib = 3 * (int)r;
        float v0 = net[gidx[ib]], v1 = net[gidx[ib + 1]], v2 = net[gidx[ib + 2]];
        const float* t = &sT[threadIdx.x * 27];
#pragma unroll
        for (int j = 0; j < 9; j++)
            o[j] = t[3 * j] * v0 + t[3 * j + 1] * v1 + t[3 * j + 2] * v2;
    }
    __syncthreads();
    float* sO = sT;
    if (r < RROT) {
#pragma unroll
        for (int j = 0; j < 9; j++) sO[threadIdx.x * 9 + j] = o[j];
    }
    __syncthreads();
    long ob = 2 + base * 9;
    for (int i = threadIdx.x; i < 256 * 9; i += 256) {
        long gi = ob + i;
        if (gi < (long)ROTLEN) g_rot[gi] = sO[i];
    }
    if (blockIdx.x == 0 && threadIdx.x == 0) { g_rot[0] = 0.0f; g_rot[1] = 1.0f; }
}

// ---------------- Kernel 2: H gather ----------------
__global__ void k_hgather(const int* __restrict__ oper, float* __restrict__ outH) {
    int i = blockIdx.x * blockDim.x + threadIdx.x;
    int4 idx = ((const int4*)oper)[i];
    float4 v;
    v.x = g_rot[idx.x]; v.y = g_rot[idx.y]; v.z = g_rot[idx.z]; v.w = g_rot[idx.w];
    ((float4*)outH)[i] = v;
}

// ---------------- Kernel 3: dQ, ep, ener2, F, fockp ----------------
__global__ void k_pre(const float* __restrict__ S, const float* __restrict__ G,
                      const float* __restrict__ rho, const float* __restrict__ qn,
                      const float* __restrict__ phiS, const float* __restrict__ H,
                      float* __restrict__ out_dQ) {
    extern __shared__ float sm[];
    float* b1 = sm;          // S, then T1
    float* b2 = sm + 4160;   // F
    float* b3 = sm + 8320;   // phiS
    __shared__ float sdQ[64], sep[64];
    int g = blockIdx.x, tid = threadIdx.x;
    const float* Sg = S + (size_t)g * 4096;
    const float* Gg = G + (size_t)g * 4096;
    const float* Rg = rho + (size_t)g * 4096;
    const float* Pg = phiS + (size_t)g * 4096;
    const float* Hg = H + (size_t)g * 4096;

    for (int i = tid; i < 4096; i += 256) {
        int r = i >> 6, c = i & 63;
        b1[r * 65 + c] = Sg[i];
        b3[r * 65 + c] = Pg[i];
    }
    __syncthreads();
    int w = tid >> 5, lane = tid & 31;
    for (int rr = 0; rr < 8; rr++) {
        int row = w * 8 + rr;
        float x = Rg[row * 64 + lane] * b1[row * 65 + lane]
                + Rg[row * 64 + lane + 32] * b1[row * 65 + lane + 32];
        for (int o = 16; o; o >>= 1) x += __shfl_xor_sync(0xffffffffu, x, o);
        if (!lane) sdQ[row] = qn[g * 64 + row] - x;
    }
    __syncthreads();
    for (int rr = 0; rr < 8; rr++) {
        int row = w * 8 + rr;
        float x = Gg[row * 64 + lane] * sdQ[lane]
                + Gg[row * 64 + lane + 32] * sdQ[lane + 32];
        for (int o = 16; o; o >>= 1) x += __shfl_xor_sync(0xffffffffu, x, o);
        if (!lane) sep[row] = x;
    }
    __syncthreads();
    if (tid < 64) out_dQ[g * 64 + tid] = sdQ[tid];
    if (tid < 32) {
        float e = sdQ[tid] * sep[tid] + sdQ[tid + 32] * sep[tid + 32];
        for (int o = 16; o; o >>= 1) e += __shfl_xor_sync(0xffffffffu, e, o);
        if (!tid) g_ener2[g] = 0.5f * e;
    }
    for (int i = tid; i < 4096; i += 256) {
        int r = i >> 6, c = i & 63;
        b2[r * 65 + c] = Hg[i] - 0.5f * b1[r * 65 + c] * (sep[r] + sep[c]);
    }
    __syncthreads();
    int tx = tid & 15, ty = tid >> 4, r0 = ty * 4, c0 = tx * 4;
    float acc[4][4];
#pragma unroll
    for (int i = 0; i < 4; i++)
#pragma unroll
        for (int j = 0; j < 4; j++) acc[i][j] = 0.0f;
    for (int k = 0; k < 64; k++) {
        float a0 = b2[(r0 + 0) * 65 + k], a1 = b2[(r0 + 1) * 65 + k];
        float a2 = b2[(r0 + 2) * 65 + k], a3 = b2[(r0 + 3) * 65 + k];
        float q0 = b3[k * 65 + c0], q1 = b3[k * 65 + c0 + 1];
        float q2 = b3[k * 65 + c0 + 2], q3 = b3[k * 65 + c0 + 3];
        acc[0][0] += a0 * q0; acc[0][1] += a0 * q1; acc[0][2] += a0 * q2; acc[0][3] += a0 * q3;
        acc[1][0] += a1 * q0; acc[1][1] += a1 * q1; acc[1][2] += a1 * q2; acc[1][3] += a1 * q3;
        acc[2][0] += a2 * q0; acc[2][1] += a2 * q1; acc[2][2] += a2 * q2; acc[2][3] += a2 * q3;
        acc[3][0] += a3 * q0; acc[3][1] += a3 * q1; acc[3][2] += a3 * q2; acc[3][3] += a3 * q3;
    }
    __syncthreads();
#pragma unroll
    for (int i = 0; i < 4; i++)
#pragma unroll
        for (int j = 0; j < 4; j++) b1[(r0 + i) * 65 + c0 + j] = acc[i][j];
    __syncthreads();
#pragma unroll
    for (int i = 0; i < 4; i++)
#pragma unroll
        for (int j = 0; j < 4; j++) acc[i][j] = 0.0f;
    for (int k = 0; k < 64; k++) {
        float a0 = b3[k * 65 + r0 + 0], a1 = b3[k * 65 + r0 + 1];
        float a2 = b3[k * 65 + r0 + 2], a3 = b3[k * 65 + r0 + 3];
        float q0 = b1[k * 65 + c0], q1 = b1[k * 65 + c0 + 1];
        float q2 = b1[k * 65 + c0 + 2], q3 = b1[k * 65 + c0 + 3];
        acc[0][0] += a0 * q0; acc[0][1] += a0 * q1; acc[0][2] += a0 * q2; acc[0][3] += a0 * q3;
        acc[1][0] += a1 * q0; acc[1][1] += a1 * q1; acc[1][2] += a1 * q2; acc[1][3] += a1 * q3;
        acc[2][0] += a2 * q0; acc[2][1] += a2 * q1; acc[2][2] += a2 * q2; acc[2][3] += a2 * q3;
        acc[3][0] += a3 * q0; acc[3][1] += a3 * q1; acc[3][2] += a3 * q2; acc[3][3] += a3 * q3;
    }
    float* fo = g_fockp + (size_t)g * 4096;
#pragma unroll
    for (int i = 0; i < 4; i++)
#pragma unroll
        for (int j = 0; j < 4; j++) fo[(r0 + i) * 64 + c0 + j] = acc[i][j];
}

// ---------------- Kernel 4: Erep ----------------
__global__ void k_erep(const float* __restrict__ net, const int* __restrict__ gr,
                       const int* __restrict__ seg, float* __restrict__ out_erep) {
    __shared__ int sbnd[2];
    __shared__ float sred[256];
    int g = blockIdx.x, tid = threadIdx.x;
    if (tid < 2) {
        int target = g + tid, lo = 0, hi = EREPN;
        while (lo < hi) {
            int mid = (lo + hi) >> 1;
            if (seg[mid] < target) lo = mid + 1; else hi = mid;
        }
        sbnd[tid] = lo;
    }
    __syncthreads();
    float s = 0.0f;
    for (int i = sbnd[0] + tid; i < sbnd[1]; i += 256) s += net[gr[i]];
    sred[tid] = s;
    __syncthreads();
    for (int o = 128; o; o >>= 1) {
        if (tid < o) sred[tid] += sred[tid + o];
        __syncthreads();
    }
    if (!tid) out_erep[g] = sred[0];
}

// ---------------- Kernel 5: register-resident Brent-Luk Jacobi + post-eig ----
// Storage: warp w owns storage columns 8w..8w+7; lane l holds rows (2l, 2l+1)
// of each owned column. Pivot pairs are fixed in storage space: (2i, 2i+1).
// Data migrates each round by the static round-robin permutation:
//   pos0 fixed; pos2<-pos1; even s>=4 <- s-2; odd s<=61 <- s+2; pos63<-pos62.
// After 63 rounds (one sweep) storage order returns to identity.
__global__ void __launch_bounds__(256) k_eig(const float* __restrict__ phiS,
                                             const float* __restrict__ occ,
                                             const float* __restrict__ outH,
                                             float* __restrict__ out) {
    extern __shared__ float sm[];
    float* b1 = sm;          // staging / xcol exchange / orb_filled
    float* b2 = sm + 4160;   // V dump for post-GEMMs
    float* b3 = sm + 8320;   // phiS
    __shared__ float sc[32], ss[32], sd[64], sred[256], sfrob;
    __shared__ int scol[64], sflag;
    int g = blockIdx.x, tid = threadIdx.x;
    int w = tid >> 5, l = tid & 31;
    const float* fp = g_fockp + (size_t)g * 4096;
    const float* Pg = phiS + (size_t)g * 4096;

    // stage symmetrized fockp into b1, phiS into b3
    for (int i = tid; i < 4096; i += 256) {
        int r = i >> 6, c = i & 63;
        b1[r * 65 + c] = 0.5f * (fp[i] + fp[c * 64 + r]);
        b3[r * 65 + c] = Pg[i];
    }
    __syncthreads();

    float A0[8], A1[8], V0[8], V1[8];
    float fl = 0.0f;
#pragma unroll
    for (int j = 0; j < 8; j++) {
        int cg = 8 * w + j;
        A0[j] = b1[(2 * l) * 65 + cg];
        A1[j] = b1[(2 * l + 1) * 65 + cg];
        fl += A0[j] * A0[j] + A1[j] * A1[j];
        V0[j] = (2 * l == cg) ? 1.0f : 0.0f;
        V1[j] = (2 * l + 1 == cg) ? 1.0f : 0.0f;
    }
    sred[tid] = fl;
    __syncthreads();     // also: done reading b1, free for xcol use
    for (int o = 128; o; o >>= 1) {
        if (tid < o) sred[tid] += sred[tid + o];
        __syncthreads();
    }
    if (!tid) { sfrob = sred[0]; sflag = 0; }
    __syncthreads();

    float2* xb = (float2*)b1;

    for (int sweep = 0; sweep < 16; sweep++) {
        for (int rnd = 0; rnd < 63; rnd++) {
            // phase A: lanes 4w..4w+3 compute their slot's rotation (slot = l)
            if ((l >> 2) == w) {
                int j = l & 3;
                float app = A0[2 * j], aqq = A1[2 * j + 1], apq = A0[2 * j + 1];
                float c, s;
                if (fabsf(apq) < 1e-30f) { c = 1.0f; s = 0.0f; }
                else {
                    float tau = (aqq - app) / (2.0f * apq);
                    float t = copysignf(1.0f / (fabsf(tau) + sqrtf(1.0f + tau * tau)), tau);
                    c = rsqrtf(1.0f + t * t);
                    s = t * c;
                }
                sc[l] = c; ss[l] = s;
            }
            __syncthreads();
            float cr = sc[l], sr = ss[l];   // coefficients for this lane's row pair
            // phase B: right rotation on column pairs (A and V)
#pragma unroll
            for (int jj = 0; jj < 4; jj++) {
                float cc = sc[4 * w + jj], s2 = ss[4 * w + jj];
                int a = 2 * jj, b = a + 1;
                float x, y;
                x = A0[a]; y = A0[b]; A0[a] = cc * x - s2 * y; A0[b] = s2 * x + cc * y;
                x = A1[a]; y = A1[b]; A1[a] = cc * x - s2 * y; A1[b] = s2 * x + cc * y;
                x = V0[a]; y = V0[b]; V0[a] = cc * x - s2 * y; V0[b] = s2 * x + cc * y;
                x = V1[a]; y = V1[b]; V1[a] = cc * x - s2 * y; V1[b] = s2 * x + cc * y;
            }
            // left rotation (in-thread row pair) + row migration on A
#pragma unroll
            for (int j = 0; j < 8; j++) {
                float x = A0[j], y = A1[j];
                float r0 = cr * x - sr * y;
                float r1 = sr * x + cr * y;
                float up = __shfl_up_sync(0xffffffffu, r0, 1);
                float bc = __shfl_sync(0xffffffffu, r1, 0);
                float dn = __shfl_down_sync(0xffffffffu, r1, 1);
                A0[j] = (l == 0) ? r0 : ((l == 1) ? bc : up);
                A1[j] = (l == 31) ? r0 : dn;
            }
            // stage boundary columns (post-rotation, post-row-migration)
            xb[(w * 4 + 0) * 32 + l] = make_float2(A0[6], A1[6]);
            xb[(w * 4 + 1) * 32 + l] = make_float2(A0[1], A1[1]);
            xb[(w * 4 + 2) * 32 + l] = make_float2(V0[6], V1[6]);
            xb[(w * 4 + 3) * 32 + l] = make_float2(V0[1], V1[1]);
            __syncthreads();
            // phase C: column migration (static renames + boundary reads)
            {
                float a1_0 = A0[1], a1_1 = A1[1], a6_0 = A0[6], a6_1 = A1[6];
                float v1_0 = V0[1], v1_1 = V1[1], v6_0 = V0[6], v6_1 = V1[6];
                // even chain (descending): new6<-4, 4<-2, 2<-(0 or special), 0<-recv
                A0[6] = A0[4]; A1[6] = A1[4]; A0[4] = A0[2]; A1[4] = A1[2];
                V0[6] = V0[4]; V1[6] = V1[4]; V0[4] = V0[2]; V1[4] = V1[2];
                if (w == 0) { A0[2] = a1_0; A1[2] = a1_1; V0[2] = v1_0; V1[2] = v1_1; }
                else        { A0[2] = A0[0]; A1[2] = A1[0]; V0[2] = V0[0]; V1[2] = V1[0]; }
                if (w > 0) {
                    float2 ra = xb[((w - 1) * 4 + 0) * 32 + l];
                    float2 rv = xb[((w - 1) * 4 + 2) * 32 + l];
                    A0[0] = ra.x; A1[0] = ra.y; V0[0] = rv.x; V1[0] = rv.y;
                }
                // odd chain (ascending): new1<-3, 3<-5, 5<-7, 7<-(recv or special)
                A0[1] = A0[3]; A1[1] = A1[3]; A0[3] = A0[5]; A1[3] = A1[5];
                A0[5] = A0[7]; A1[5] = A1[7];
                V0[1] = V0[3]; V1[1] = V1[3]; V0[3] = V0[5]; V1[3] = V1[5];
                V0[5] = V0[7]; V1[5] = V1[7];
                if (w == 7) { A0[7] = a6_0; A1[7] = a6_1; V0[7] = v6_0; V1[7] = v6_1; }
                else {
                    float2 ra = xb[((w + 1) * 4 + 1) * 32 + l];
                    float2 rv = xb[((w + 1) * 4 + 3) * 32 + l];
                    A0[7] = ra.x; A1[7] = ra.y; V0[7] = rv.x; V1[7] = rv.y;
                }
            }
        }
        // sweep-end convergence check (storage = identity order here)
        float off = 0.0f;
#pragma unroll
        for (int j = 0; j < 8; j++) {
            int cg = 8 * w + j;
            if (2 * l != cg)     off += A0[j] * A0[j];
            if (2 * l + 1 != cg) off += A1[j] * A1[j];
        }
        sred[tid] = off;
        __syncthreads();
        for (int o = 128; o; o >>= 1) {
            if (tid < o) sred[tid] += sred[tid + o];
            __syncthreads();
        }
        if (!tid && sred[0] <= 1e-11f * sfrob) sflag = 1;
        __syncthreads();
        if (sflag) break;
    }

    // dump V to shared, extract eigenvalues
#pragma unroll
    for (int j = 0; j < 8; j++) {
        int cg = 8 * w + j;
        b2[(2 * l) * 65 + cg] = V0[j];
        b2[(2 * l + 1) * 65 + cg] = V1[j];
        if (2 * l == cg)     sd[cg] = A0[j];
        if (2 * l + 1 == cg) sd[cg] = A1[j];
    }
    __syncthreads();
    // eigenvalue rank sort (ascending, stable)
    if (tid < 64) {
        float d = sd[tid];
        int r = 0;
        for (int jj = 0; jj < 64; jj++)
            r += (sd[jj] < d) || (sd[jj] == d && jj < tid);
        scol[r] = tid;
        out[OFF_EORB + g * 64 + r] = d;
    }
    __syncthreads();

    int tx = tid & 15, ty = tid >> 4, r0 = ty * 4, c0 = tx * 4;
    const float* Og = occ + (size_t)g * 4096;
    const float* Hg = outH + (size_t)g * 4096;
    float acc[4][4];
    // orb_filled = occ * (phiS @ V[:, perm])  -> b1
    int j0 = scol[c0], j1 = scol[c0 + 1], j2 = scol[c0 + 2], j3 = scol[c0 + 3];
#pragma unroll
    for (int i = 0; i < 4; i++)
#pragma unroll
        for (int j = 0; j < 4; j++) acc[i][j] = 0.0f;
    for (int k = 0; k < 64; k++) {
        float a0 = b3[(r0 + 0) * 65 + k], a1 = b3[(r0 + 1) * 65 + k];
        float a2 = b3[(r0 + 2) * 65 + k], a3 = b3[(r0 + 3) * 65 + k];
        float q0 = b2[k * 65 + j0], q1 = b2[k * 65 + j1];
        float q2 = b2[k * 65 + j2], q3 = b2[k * 65 + j3];
        acc[0][0] += a0 * q0; acc[0][1] += a0 * q1; acc[0][2] += a0 * q2; acc[0][3] += a0 * q3;
        acc[1][0] += a1 * q0; acc[1][1] += a1 * q1; acc[1][2] += a1 * q2; acc[1][3] += a1 * q3;
        acc[2][0] += a2 * q0; acc[2][1] += a2 * q1; acc[2][2] += a2 * q2; acc[2][3] += a2 * q3;
        acc[3][0] += a3 * q0; acc[3][1] += a3 * q1; acc[3][2] += a3 * q2; acc[3][3] += a3 * q3;
    }
    __syncthreads();
#pragma unroll
    for (int i = 0; i < 4; i++)
#pragma unroll
        for (int j = 0; j < 4; j++)
            b1[(r0 + i) * 65 + c0 + j] = Og[(r0 + i) * 64 + c0 + j] * acc[i][j];
    __syncthreads();
    // rho_out = 2 * orbf @ orbf^T ; ener1 = sum(rho_out * H)
#pragma unroll
    for (int i = 0; i < 4; i++)
#pragma unroll
        for (int j = 0; j < 4; j++) acc[i][j] = 0.0f;
    for (int k = 0; k < 64; k++) {
        float a0 = b1[(r0 + 0) * 65 + k], a1 = b1[(r0 + 1) * 65 + k];
        float a2 = b1[(r0 + 2) * 65 + k], a3 = b1[(r0 + 3) * 65 + k];
        float q0 = b1[(c0 + 0) * 65 + k], q1 = b1[(c0 + 1) * 65 + k];
        float q2 = b1[(c0 + 2) * 65 + k], q3 = b1[(c0 + 3) * 65 + k];
        acc[0][0] += a0 * q0; acc[0][1] += a0 * q1; acc[0][2] += a0 * q2; acc[0][3] += a0 * q3;
        acc[1][0] += a1 * q0; acc[1][1] += a1 * q1; acc[1][2] += a1 * q2; acc[1][3] += a1 * q3;
        acc[2][0] += a2 * q0; acc[2][1] += a2 * q1; acc[2][2] += a2 * q2; acc[2][3] += a2 * q3;
        acc[3][0] += a3 * q0; acc[3][1] += a3 * q1; acc[3][2] += a3 * q2; acc[3][3] += a3 * q3;
    }
    float* Ro = out + OFF_RHO + (size_t)g * 4096;
    float e1 = 0.0f;
#pragma unroll
    for (int i = 0; i < 4; i++)
#pragma unroll
        for (int j = 0; j < 4; j++) {
            float v = 2.0f * acc[i][j];
            Ro[(r0 + i) * 64 + c0 + j] = v;
            e1 += v * Hg[(r0 + i) * 64 + c0 + j];
        }
    sred[tid] = e1;
    __syncthreads();
    for (int o = 128; o; o >>= 1) {
        if (tid < o) sred[tid] += sred[tid + o];
        __syncthreads();
    }
    if (!tid) out[OFF_EELEC + g] = sred[0] + g_ener2[g];
}

// ---------------- Kernel 6: Eref ----------------
__global__ void k_eref(const float* __restrict__ zc, const float* __restrict__ rv,
                       float* __restrict__ out) {
    if (threadIdx.x == 0) {
        float s = 0.0f;
        for (int i = 0; i < 7; i++) s += zc[i] * rv[i];
        out[OFF_EREF] = s;
    }
}

extern "C" void kernel_launch(void* const* d_in, const int* in_sizes, int n_in,
                              void* d_out, int out_size) {
    const float* net   = (const float*)d_in[0];
    const float* rotT  = (const float*)d_in[1];
    const float* S     = (const float*)d_in[2];
    const float* G     = (const float*)d_in[3];
    const float* rho   = (const float*)d_in[4];
    const float* qn    = (const float*)d_in[5];
    const float* occ   = (const float*)d_in[6];
    const float* phiS  = (const float*)d_in[7];
    const float* zc    = (const float*)d_in[8];
    const float* rv    = (const float*)d_in[9];
    const int* grot    = (const int*)d_in[10];
    const int* goper   = (const int*)d_in[11];
    const int* grep    = (const int*)d_in[12];
    const int* segrep  = (const int*)d_in[13];
    float* out = (float*)d_out;

    static bool attr_done = false;
    if (!attr_done) {
        cudaFuncSetAttribute(k_pre, cudaFuncAttributeMaxDynamicSharedMemorySize, 49920);
        cudaFuncSetAttribute(k_eig, cudaFuncAttributeMaxDynamicSharedMemorySize, 49920);
        attr_done = true;
    }

    k_rot<<<(RROT + 255) / 256, 256>>>(net, rotT, grot);
    k_hgather<<<NGBB / 4 / 256, 256>>>(goper, out + OFF_H);
    k_pre<<<NGEO, 256, 49920>>>(S, G, rho, qn, phiS, out + OFF_H, out + OFF_DQ);
    k_erep<<<NGEO, 256>>>(net, grep, segrep, out + OFF_EREP);
    k_eig<<<NGEO, 256, 49920>>>(phiS, occ, out + OFF_H, out);
    k_eref<<<1, 32>>>(zc, rv, out);
}

// round 5
// speedup vs baseline: 1.8575x; 1.3964x over previous
#include <cuda_runtime.h>
#include <math.h>

#define NGEO 1024
#define RROT 1000000
#define EREPN 2000000
#define NGBB (NGEO*4096)
#define ROTLEN (2 + RROT*9)

#define OFF_H     0
#define OFF_DQ    4194304
#define OFF_EREP  4259840
#define OFF_EORB  4260864
#define OFF_RHO   4326400
#define OFF_EELEC 8520704
#define OFF_EREF  8521728

__device__ float g_rot[ROTLEN];
__device__ float g_fockp[NGBB];
__device__ float g_ener2[NGEO];
__device__ float g_V[NGBB];
__device__ int   g_perm[NGEO * 64];

// ---------------- Kernel 1: rotation stage ----------------
__global__ void k_rot(const float* __restrict__ net, const float* __restrict__ T,
                      const int* __restrict__ gidx) {
    __shared__ float sT[256 * 27];
    const long base = (long)blockIdx.x * 256;
    const long tb = base * 27;
    const long tmax = (long)RROT * 27;
    for (int i = threadIdx.x; i < 256 * 27; i += 256) {
        long gi = tb + i;
        if (gi < tmax) sT[i] = T[gi];
    }
    __syncthreads();
    long r = base + threadIdx.x;
    float o[9];
    if (r < RROT) {
        int ib = 3 * (int)r;
        float v0 = net[gidx[ib]], v1 = net[gidx[ib + 1]], v2 = net[gidx[ib + 2]];
        const float* t = &sT[threadIdx.x * 27];
#pragma unroll
        for (int j = 0; j < 9; j++)
            o[j] = t[3 * j] * v0 + t[3 * j + 1] * v1 + t[3 * j + 2] * v2;
    }
    __syncthreads();
    float* sO = sT;
    if (r < RROT) {
#pragma unroll
        for (int j = 0; j < 9; j++) sO[threadIdx.x * 9 + j] = o[j];
    }
    __syncthreads();
    long ob = 2 + base * 9;
    for (int i = threadIdx.x; i < 256 * 9; i += 256) {
        long gi = ob + i;
        if (gi < (long)ROTLEN) g_rot[gi] = sO[i];
    }
    if (blockIdx.x == 0 && threadIdx.x == 0) { g_rot[0] = 0.0f; g_rot[1] = 1.0f; }
}

// ---------------- Kernel 2: H gather ----------------
__global__ void k_hgather(const int* __restrict__ oper, float* __restrict__ outH) {
    int i = blockIdx.x * blockDim.x + threadIdx.x;
    int4 idx = ((const int4*)oper)[i];
    float4 v;
    v.x = g_rot[idx.x]; v.y = g_rot[idx.y]; v.z = g_rot[idx.z]; v.w = g_rot[idx.w];
    ((float4*)outH)[i] = v;
}

// ---------------- Kernel 3: dQ, ep, ener2, F, fockp ----------------
__global__ void k_pre(const float* __restrict__ S, const float* __restrict__ G,
                      const float* __restrict__ rho, const float* __restrict__ qn,
                      const float* __restrict__ phiS, const float* __restrict__ H,
                      float* __restrict__ out_dQ) {
    extern __shared__ float sm[];
    float* b1 = sm;          // S, then T1
    float* b2 = sm + 4160;   // F
    float* b3 = sm + 8320;   // phiS
    __shared__ float sdQ[64], sep[64];
    int g = blockIdx.x, tid = threadIdx.x;
    const float* Sg = S + (size_t)g * 4096;
    const float* Gg = G + (size_t)g * 4096;
    const float* Rg = rho + (size_t)g * 4096;
    const float* Pg = phiS + (size_t)g * 4096;
    const float* Hg = H + (size_t)g * 4096;

    for (int i = tid; i < 4096; i += 256) {
        int r = i >> 6, c = i & 63;
        b1[r * 65 + c] = Sg[i];
        b3[r * 65 + c] = Pg[i];
    }
    __syncthreads();
    int w = tid >> 5, lane = tid & 31;
    for (int rr = 0; rr < 8; rr++) {
        int row = w * 8 + rr;
        float x = Rg[row * 64 + lane] * b1[row * 65 + lane]
                + Rg[row * 64 + lane + 32] * b1[row * 65 + lane + 32];
        for (int o = 16; o; o >>= 1) x += __shfl_xor_sync(0xffffffffu, x, o);
        if (!lane) sdQ[row] = qn[g * 64 + row] - x;
    }
    __syncthreads();
    for (int rr = 0; rr < 8; rr++) {
        int row = w * 8 + rr;
        float x = Gg[row * 64 + lane] * sdQ[lane]
                + Gg[row * 64 + lane + 32] * sdQ[lane + 32];
        for (int o = 16; o; o >>= 1) x += __shfl_xor_sync(0xffffffffu, x, o);
        if (!lane) sep[row] = x;
    }
    __syncthreads();
    if (tid < 64) out_dQ[g * 64 + tid] = sdQ[tid];
    if (tid < 32) {
        float e = sdQ[tid] * sep[tid] + sdQ[tid + 32] * sep[tid + 32];
        for (int o = 16; o; o >>= 1) e += __shfl_xor_sync(0xffffffffu, e, o);
        if (!tid) g_ener2[g] = 0.5f * e;
    }
    for (int i = tid; i < 4096; i += 256) {
        int r = i >> 6, c = i & 63;
        b2[r * 65 + c] = Hg[i] - 0.5f * b1[r * 65 + c] * (sep[r] + sep[c]);
    }
    __syncthreads();
    int tx = tid & 15, ty = tid >> 4, r0 = ty * 4, c0 = tx * 4;
    float acc[4][4];
#pragma unroll
    for (int i = 0; i < 4; i++)
#pragma unroll
        for (int j = 0; j < 4; j++) acc[i][j] = 0.0f;
    for (int k = 0; k < 64; k++) {
        float a0 = b2[(r0 + 0) * 65 + k], a1 = b2[(r0 + 1) * 65 + k];
        float a2 = b2[(r0 + 2) * 65 + k], a3 = b2[(r0 + 3) * 65 + k];
        float q0 = b3[k * 65 + c0], q1 = b3[k * 65 + c0 + 1];
        float q2 = b3[k * 65 + c0 + 2], q3 = b3[k * 65 + c0 + 3];
        acc[0][0] += a0 * q0; acc[0][1] += a0 * q1; acc[0][2] += a0 * q2; acc[0][3] += a0 * q3;
        acc[1][0] += a1 * q0; acc[1][1] += a1 * q1; acc[1][2] += a1 * q2; acc[1][3] += a1 * q3;
        acc[2][0] += a2 * q0; acc[2][1] += a2 * q1; acc[2][2] += a2 * q2; acc[2][3] += a2 * q3;
        acc[3][0] += a3 * q0; acc[3][1] += a3 * q1; acc[3][2] += a3 * q2; acc[3][3] += a3 * q3;
    }
    __syncthreads();
#pragma unroll
    for (int i = 0; i < 4; i++)
#pragma unroll
        for (int j = 0; j < 4; j++) b1[(r0 + i) * 65 + c0 + j] = acc[i][j];
    __syncthreads();
#pragma unroll
    for (int i = 0; i < 4; i++)
#pragma unroll
        for (int j = 0; j < 4; j++) acc[i][j] = 0.0f;
    for (int k = 0; k < 64; k++) {
        float a0 = b3[k * 65 + r0 + 0], a1 = b3[k * 65 + r0 + 1];
        float a2 = b3[k * 65 + r0 + 2], a3 = b3[k * 65 + r0 + 3];
        float q0 = b1[k * 65 + c0], q1 = b1[k * 65 + c0 + 1];
        float q2 = b1[k * 65 + c0 + 2], q3 = b1[k * 65 + c0 + 3];
        acc[0][0] += a0 * q0; acc[0][1] += a0 * q1; acc[0][2] += a0 * q2; acc[0][3] += a0 * q3;
        acc[1][0] += a1 * q0; acc[1][1] += a1 * q1; acc[1][2] += a1 * q2; acc[1][3] += a1 * q3;
        acc[2][0] += a2 * q0; acc[2][1] += a2 * q1; acc[2][2] += a2 * q2; acc[2][3] += a2 * q3;
        acc[3][0] += a3 * q0; acc[3][1] += a3 * q1; acc[3][2] += a3 * q2; acc[3][3] += a3 * q3;
    }
    float* fo = g_fockp + (size_t)g * 4096;
#pragma unroll
    for (int i = 0; i < 4; i++)
#pragma unroll
        for (int j = 0; j < 4; j++) fo[(r0 + i) * 64 + c0 + j] = acc[i][j];
}

// ---------------- Kernel 4: Erep ----------------
__global__ void k_erep(const float* __restrict__ net, const int* __restrict__ gr,
                       const int* __restrict__ seg, float* __restrict__ out_erep) {
    __shared__ int sbnd[2];
    __shared__ float sred[256];
    int g = blockIdx.x, tid = threadIdx.x;
    if (tid < 2) {
        int target = g + tid, lo = 0, hi = EREPN;
        while (lo < hi) {
            int mid = (lo + hi) >> 1;
            if (seg[mid] < target) lo = mid + 1; else hi = mid;
        }
        sbnd[tid] = lo;
    }
    __syncthreads();
    float s = 0.0f;
    for (int i = sbnd[0] + tid; i < sbnd[1]; i += 256) s += net[gr[i]];
    sred[tid] = s;
    __syncthreads();
    for (int o = 128; o; o >>= 1) {
        if (tid < o) sred[tid] += sred[tid + o];
        __syncthreads();
    }
    if (!tid) out_erep[g] = sred[0];
}

// ---------------- Kernel 5: Brent-Luk Jacobi (lean registers) ----------------
// Storage: warp w owns cols 8w..8w+7; lane l holds rows (2l, 2l+1).
// Pivot pairs fixed at (2i,2i+1) in storage; data migrates by the static
// round-robin permutation; identity order returns every 63 rounds.
__global__ void __launch_bounds__(256, 4) k_jac(float* __restrict__ out) {
    extern __shared__ float sm[];           // 4160 floats: staging / exchange
    __shared__ float sc[32], ss[32], sd[64], sred[256], sfrob;
    __shared__ int sflag;
    int g = blockIdx.x, tid = threadIdx.x;
    int w = tid >> 5, l = tid & 31;
    const float* fp = g_fockp + (size_t)g * 4096;

    // stage symmetrized fockp
    for (int i = tid; i < 4096; i += 256) {
        int r = i >> 6, c = i & 63;
        sm[r * 65 + c] = 0.5f * (fp[i] + fp[c * 64 + r]);
    }
    __syncthreads();

    float A0[8], A1[8], V0[8], V1[8];
    float fl = 0.0f;
#pragma unroll
    for (int j = 0; j < 8; j++) {
        int cg = 8 * w + j;
        A0[j] = sm[(2 * l) * 65 + cg];
        A1[j] = sm[(2 * l + 1) * 65 + cg];
        fl += A0[j] * A0[j] + A1[j] * A1[j];
        V0[j] = (2 * l == cg) ? 1.0f : 0.0f;
        V1[j] = (2 * l + 1 == cg) ? 1.0f : 0.0f;
    }
    sred[tid] = fl;
    __syncthreads();
    for (int o = 128; o; o >>= 1) {
        if (tid < o) sred[tid] += sred[tid + o];
        __syncthreads();
    }
    if (!tid) { sfrob = sred[0]; sflag = 0; }
    __syncthreads();

    float2* xb = (float2*)sm;

    for (int sweep = 0; sweep < 16; sweep++) {
        for (int rnd = 0; rnd < 63; rnd++) {
            if ((l >> 2) == w) {
                int j = l & 3;
                float app = A0[2 * j], aqq = A1[2 * j + 1], apq = A0[2 * j + 1];
                float c, s;
                if (fabsf(apq) < 1e-30f) { c = 1.0f; s = 0.0f; }
                else {
                    float tau = (aqq - app) / (2.0f * apq);
                    float t = copysignf(1.0f / (fabsf(tau) + sqrtf(1.0f + tau * tau)), tau);
                    c = rsqrtf(1.0f + t * t);
                    s = t * c;
                }
                sc[l] = c; ss[l] = s;
            }
            __syncthreads();
            float cr = sc[l], sr = ss[l];
            // right rotation on column pairs
#pragma unroll
            for (int jj = 0; jj < 4; jj++) {
                float cc = sc[4 * w + jj], s2 = ss[4 * w + jj];
                int a = 2 * jj, b = a + 1;
                float x, y;
                x = A0[a]; y = A0[b]; A0[a] = cc * x - s2 * y; A0[b] = s2 * x + cc * y;
                x = A1[a]; y = A1[b]; A1[a] = cc * x - s2 * y; A1[b] = s2 * x + cc * y;
                x = V0[a]; y = V0[b]; V0[a] = cc * x - s2 * y; V0[b] = s2 * x + cc * y;
                x = V1[a]; y = V1[b]; V1[a] = cc * x - s2 * y; V1[b] = s2 * x + cc * y;
            }
            // left rotation + row migration (2 shuffles per column)
#pragma unroll
            for (int j = 0; j < 8; j++) {
                float x = A0[j], y = A1[j];
                float r0 = cr * x - sr * y;
                float r1 = sr * x + cr * y;
                float tmp = (l == 0) ? r1 : r0;
                float up = __shfl_up_sync(0xffffffffu, tmp, 1);
                float dn = __shfl_down_sync(0xffffffffu, r1, 1);
                A0[j] = (l == 0) ? r0 : up;
                A1[j] = (l == 31) ? r0 : dn;
            }
            // stage boundary columns
            xb[(w * 4 + 0) * 32 + l] = make_float2(A0[6], A1[6]);
            xb[(w * 4 + 1) * 32 + l] = make_float2(A0[1], A1[1]);
            xb[(w * 4 + 2) * 32 + l] = make_float2(V0[6], V1[6]);
            xb[(w * 4 + 3) * 32 + l] = make_float2(V0[1], V1[1]);
            __syncthreads();
            // column migration
            {
                float a1_0 = A0[1], a1_1 = A1[1], a6_0 = A0[6], a6_1 = A1[6];
                float v1_0 = V0[1], v1_1 = V1[1], v6_0 = V0[6], v6_1 = V1[6];
                A0[6] = A0[4]; A1[6] = A1[4]; A0[4] = A0[2]; A1[4] = A1[2];
                V0[6] = V0[4]; V1[6] = V1[4]; V0[4] = V0[2]; V1[4] = V1[2];
                if (w == 0) { A0[2] = a1_0; A1[2] = a1_1; V0[2] = v1_0; V1[2] = v1_1; }
                else        { A0[2] = A0[0]; A1[2] = A1[0]; V0[2] = V0[0]; V1[2] = V1[0]; }
                if (w > 0) {
                    float2 ra = xb[((w - 1) * 4 + 0) * 32 + l];
                    float2 rv = xb[((w - 1) * 4 + 2) * 32 + l];
                    A0[0] = ra.x; A1[0] = ra.y; V0[0] = rv.x; V1[0] = rv.y;
                }
                A0[1] = A0[3]; A1[1] = A1[3]; A0[3] = A0[5]; A1[3] = A1[5];
                A0[5] = A0[7]; A1[5] = A1[7];
                V0[1] = V0[3]; V1[1] = V1[3]; V0[3] = V0[5]; V1[3] = V1[5];
                V0[5] = V0[7]; V1[5] = V1[7];
                if (w == 7) { A0[7] = a6_0; A1[7] = a6_1; V0[7] = v6_0; V1[7] = v6_1; }
                else {
                    float2 ra = xb[((w + 1) * 4 + 1) * 32 + l];
                    float2 rv = xb[((w + 1) * 4 + 3) * 32 + l];
                    A0[7] = ra.x; A1[7] = ra.y; V0[7] = rv.x; V1[7] = rv.y;
                }
            }
        }
        // sweep-end convergence check (identity order)
        float off = 0.0f;
#pragma unroll
        for (int j = 0; j < 8; j++) {
            int cg = 8 * w + j;
            if (2 * l != cg)     off += A0[j] * A0[j];
            if (2 * l + 1 != cg) off += A1[j] * A1[j];
        }
        sred[tid] = off;
        __syncthreads();
        for (int o = 128; o; o >>= 1) {
            if (tid < o) sred[tid] += sred[tid + o];
            __syncthreads();
        }
        if (!tid && sred[0] <= 1e-11f * sfrob) sflag = 1;
        __syncthreads();
        if (sflag) break;
    }

    // dump V to shared staging (conflict-light), extract eigenvalues
    __syncthreads();
#pragma unroll
    for (int j = 0; j < 8; j++) {
        int cg = 8 * w + j;
        sm[(2 * l) * 65 + cg] = V0[j];
        sm[(2 * l + 1) * 65 + cg] = V1[j];
        if (2 * l == cg)     sd[cg] = A0[j];
        if (2 * l + 1 == cg) sd[cg] = A1[j];
    }
    __syncthreads();
    // coalesced V dump to global
    float* Vg = g_V + (size_t)g * 4096;
    for (int i = tid; i < 4096; i += 256) {
        int r = i >> 6, c = i & 63;
        Vg[i] = sm[r * 65 + c];
    }
    // eigenvalue rank sort (ascending, stable)
    if (tid < 64) {
        float d = sd[tid];
        int r = 0;
        for (int jj = 0; jj < 64; jj++)
            r += (sd[jj] < d) || (sd[jj] == d && jj < tid);
        g_perm[g * 64 + r] = tid;
        out[OFF_EORB + g * 64 + r] = d;
    }
}

// ---------------- Kernel 5b: post-eig GEMMs + rho_out + energies -----------
__global__ void k_post(const float* __restrict__ phiS, const float* __restrict__ occ,
                       const float* __restrict__ outH, float* __restrict__ out) {
    extern __shared__ float sm[];
    float* b1 = sm;          // orb_filled
    float* b2 = sm + 4160;   // V
    float* b3 = sm + 8320;   // phiS
    __shared__ float sred[256];
    __shared__ int scol[64];
    int g = blockIdx.x, tid = threadIdx.x;
    const float* Vg = g_V + (size_t)g * 4096;
    const float* Pg = phiS + (size_t)g * 4096;
    for (int i = tid; i < 4096; i += 256) {
        int r = i >> 6, c = i & 63;
        b2[r * 65 + c] = Vg[i];
        b3[r * 65 + c] = Pg[i];
    }
    if (tid < 64) scol[tid] = g_perm[g * 64 + tid];
    __syncthreads();

    int tx = tid & 15, ty = tid >> 4, r0 = ty * 4, c0 = tx * 4;
    const float* Og = occ + (size_t)g * 4096;
    const float* Hg = outH + (size_t)g * 4096;
    float acc[4][4];
    int j0 = scol[c0], j1 = scol[c0 + 1], j2 = scol[c0 + 2], j3 = scol[c0 + 3];
#pragma unroll
    for (int i = 0; i < 4; i++)
#pragma unroll
        for (int j = 0; j < 4; j++) acc[i][j] = 0.0f;
    for (int k = 0; k < 64; k++) {
        float a0 = b3[(r0 + 0) * 65 + k], a1 = b3[(r0 + 1) * 65 + k];
        float a2 = b3[(r0 + 2) * 65 + k], a3 = b3[(r0 + 3) * 65 + k];
        float q0 = b2[k * 65 + j0], q1 = b2[k * 65 + j1];
        float q2 = b2[k * 65 + j2], q3 = b2[k * 65 + j3];
        acc[0][0] += a0 * q0; acc[0][1] += a0 * q1; acc[0][2] += a0 * q2; acc[0][3] += a0 * q3;
        acc[1][0] += a1 * q0; acc[1][1] += a1 * q1; acc[1][2] += a1 * q2; acc[1][3] += a1 * q3;
        acc[2][0] += a2 * q0; acc[2][1] += a2 * q1; acc[2][2] += a2 * q2; acc[2][3] += a2 * q3;
        acc[3][0] += a3 * q0; acc[3][1] += a3 * q1; acc[3][2] += a3 * q2; acc[3][3] += a3 * q3;
    }
#pragma unroll
    for (int i = 0; i < 4; i++)
#pragma unroll
        for (int j = 0; j < 4; j++)
            b1[(r0 + i) * 65 + c0 + j] = Og[(r0 + i) * 64 + c0 + j] * acc[i][j];
    __syncthreads();
    // rho_out = 2 * orbf @ orbf^T ; ener1 = sum(rho_out * H)
#pragma unroll
    for (int i = 0; i < 4; i++)
#pragma unroll
        for (int j = 0; j < 4; j++) acc[i][j] = 0.0f;
    for (int k = 0; k < 64; k++) {
        float a0 = b1[(r0 + 0) * 65 + k], a1 = b1[(r0 + 1) * 65 + k];
        float a2 = b1[(r0 + 2) * 65 + k], a3 = b1[(r0 + 3) * 65 + k];
        float q0 = b1[(c0 + 0) * 65 + k], q1 = b1[(c0 + 1) * 65 + k];
        float q2 = b1[(c0 + 2) * 65 + k], q3 = b1[(c0 + 3) * 65 + k];
        acc[0][0] += a0 * q0; acc[0][1] += a0 * q1; acc[0][2] += a0 * q2; acc[0][3] += a0 * q3;
        acc[1][0] += a1 * q0; acc[1][1] += a1 * q1; acc[1][2] += a1 * q2; acc[1][3] += a1 * q3;
        acc[2][0] += a2 * q0; acc[2][1] += a2 * q1; acc[2][2] += a2 * q2; acc[2][3] += a2 * q3;
        acc[3][0] += a3 * q0; acc[3][1] += a3 * q1; acc[3][2] += a3 * q2; acc[3][3] += a3 * q3;
    }
    float* Ro = out + OFF_RHO + (size_t)g * 4096;
    float e1 = 0.0f;
#pragma unroll
    for (int i = 0; i < 4; i++)
#pragma unroll
        for (int j = 0; j < 4; j++) {
            float v = 2.0f * acc[i][j];
            Ro[(r0 + i) * 64 + c0 + j] = v;
            e1 += v * Hg[(r0 + i) * 64 + c0 + j];
        }
    sred[tid] = e1;
    __syncthreads();
    for (int o = 128; o; o >>= 1) {
        if (tid < o) sred[tid] += sred[tid + o];
        __syncthreads();
    }
    if (!tid) out[OFF_EELEC + g] = sred[0] + g_ener2[g];
}

// ---------------- Kernel 6: Eref ----------------
__global__ void k_eref(const float* __restrict__ zc, const float* __restrict__ rv,
                       float* __restrict__ out) {
    if (threadIdx.x == 0) {
        float s = 0.0f;
        for (int i = 0; i < 7; i++) s += zc[i] * rv[i];
        out[OFF_EREF] = s;
    }
}

extern "C" void kernel_launch(void* const* d_in, const int* in_sizes, int n_in,
                              void* d_out, int out_size) {
    const float* net   = (const float*)d_in[0];
    const float* rotT  = (const float*)d_in[1];
    const float* S     = (const float*)d_in[2];
    const float* G     = (const float*)d_in[3];
    const float* rho   = (const float*)d_in[4];
    const float* qn    = (const float*)d_in[5];
    const float* occ   = (const float*)d_in[6];
    const float* phiS  = (const float*)d_in[7];
    const float* zc    = (const float*)d_in[8];
    const float* rv    = (const float*)d_in[9];
    const int* grot    = (const int*)d_in[10];
    const int* goper   = (const int*)d_in[11];
    const int* grep    = (const int*)d_in[12];
    const int* segrep  = (const int*)d_in[13];
    float* out = (float*)d_out;

    static bool attr_done = false;
    if (!attr_done) {
        cudaFuncSetAttribute(k_pre, cudaFuncAttributeMaxDynamicSharedMemorySize, 49920);
        cudaFuncSetAttribute(k_post, cudaFuncAttributeMaxDynamicSharedMemorySize, 49920);
        attr_done = true;
    }

    k_rot<<<(RROT + 255) / 256, 256>>>(net, rotT, grot);
    k_hgather<<<NGBB / 4 / 256, 256>>>(goper, out + OFF_H);
    k_pre<<<NGEO, 256, 49920>>>(S, G, rho, qn, phiS, out + OFF_H, out + OFF_DQ);
    k_erep<<<NGEO, 256>>>(net, grep, segrep, out + OFF_EREP);
    k_jac<<<NGEO, 256, 16640>>>(out);
    k_post<<<NGEO, 256, 49920>>>(phiS, occ, out + OFF_H, out);
    k_eref<<<1, 32>>>(zc, rv, out);
}

// round 7
// speedup vs baseline: 1.8670x; 1.0051x over previous
#include <cuda_runtime.h>
#include <math.h>

#define NGEO 1024
#define RROT 1000000
#define EREPN 2000000
#define NGBB (NGEO*4096)
#define ROTLEN (2 + RROT*9)

#define OFF_H     0
#define OFF_DQ    4194304
#define OFF_EREP  4259840
#define OFF_EORB  4260864
#define OFF_RHO   4326400
#define OFF_EELEC 8520704
#define OFF_EREF  8521728

__device__ float g_rot[ROTLEN];
__device__ float g_fockp[NGBB];
__device__ float g_ener2[NGEO];
__device__ float g_V[NGBB];
__device__ int   g_perm[NGEO * 64];

// ---------------- Kernel 1: rotation stage ----------------
__global__ void k_rot(const float* __restrict__ net, const float* __restrict__ T,
                      const int* __restrict__ gidx) {
    __shared__ float sT[256 * 27];
    const long base = (long)blockIdx.x * 256;
    const long tb = base * 27;
    const long tmax = (long)RROT * 27;
    for (int i = threadIdx.x; i < 256 * 27; i += 256) {
        long gi = tb + i;
        if (gi < tmax) sT[i] = T[gi];
    }
    __syncthreads();
    long r = base + threadIdx.x;
    float o[9];
    if (r < RROT) {
        int ib = 3 * (int)r;
        float v0 = net[gidx[ib]], v1 = net[gidx[ib + 1]], v2 = net[gidx[ib + 2]];
        const float* t = &sT[threadIdx.x * 27];
#pragma unroll
        for (int j = 0; j < 9; j++)
            o[j] = t[3 * j] * v0 + t[3 * j + 1] * v1 + t[3 * j + 2] * v2;
    }
    __syncthreads();
    float* sO = sT;
    if (r < RROT) {
#pragma unroll
        for (int j = 0; j < 9; j++) sO[threadIdx.x * 9 + j] = o[j];
    }
    __syncthreads();
    long ob = 2 + base * 9;
    for (int i = threadIdx.x; i < 256 * 9; i += 256) {
        long gi = ob + i;
        if (gi < (long)ROTLEN) g_rot[gi] = sO[i];
    }
    if (blockIdx.x == 0 && threadIdx.x == 0) { g_rot[0] = 0.0f; g_rot[1] = 1.0f; }
}

// ---------------- Kernel 2: H gather ----------------
__global__ void k_hgather(const int* __restrict__ oper, float* __restrict__ outH) {
    int i = blockIdx.x * blockDim.x + threadIdx.x;
    int4 idx = ((const int4*)oper)[i];
    float4 v;
    v.x = g_rot[idx.x]; v.y = g_rot[idx.y]; v.z = g_rot[idx.z]; v.w = g_rot[idx.w];
    ((float4*)outH)[i] = v;
}

// ---------------- Kernel 3: dQ, ep, ener2, Fsym, fockp (symmetric) --------
__global__ void k_pre(const float* __restrict__ S, const float* __restrict__ G,
                      const float* __restrict__ rho, const float* __restrict__ qn,
                      const float* __restrict__ phiS, const float* __restrict__ H,
                      float* __restrict__ out_dQ) {
    extern __shared__ float sm[];
    float* b1 = sm;          // S, then T1
    float* b2 = sm + 4160;   // Fsym
    float* b3 = sm + 8320;   // phiS
    __shared__ float sdQ[64], sep[64];
    int g = blockIdx.x, tid = threadIdx.x;
    const float* Sg = S + (size_t)g * 4096;
    const float* Gg = G + (size_t)g * 4096;
    const float* Rg = rho + (size_t)g * 4096;
    const float* Pg = phiS + (size_t)g * 4096;
    const float* Hg = H + (size_t)g * 4096;

    for (int i = tid; i < 4096; i += 256) {
        int r = i >> 6, c = i & 63;
        b1[r * 65 + c] = Sg[i];
        b3[r * 65 + c] = Pg[i];
    }
    __syncthreads();
    int w = tid >> 5, lane = tid & 31;
    for (int rr = 0; rr < 8; rr++) {
        int row = w * 8 + rr;
        float x = Rg[row * 64 + lane] * b1[row * 65 + lane]
                + Rg[row * 64 + lane + 32] * b1[row * 65 + lane + 32];
        for (int o = 16; o; o >>= 1) x += __shfl_xor_sync(0xffffffffu, x, o);
        if (!lane) sdQ[row] = qn[g * 64 + row] - x;
    }
    __syncthreads();
    for (int rr = 0; rr < 8; rr++) {
        int row = w * 8 + rr;
        float x = Gg[row * 64 + lane] * sdQ[lane]
                + Gg[row * 64 + lane + 32] * sdQ[lane + 32];
        for (int o = 16; o; o >>= 1) x += __shfl_xor_sync(0xffffffffu, x, o);
        if (!lane) sep[row] = x;
    }
    __syncthreads();
    if (tid < 64) out_dQ[g * 64 + tid] = sdQ[tid];
    if (tid < 32) {
        float e = sdQ[tid] * sep[tid] + sdQ[tid + 32] * sep[tid + 32];
        for (int o = 16; o; o >>= 1) e += __shfl_xor_sync(0xffffffffu, e, o);
        if (!tid) g_ener2[g] = 0.5f * e;
    }
    // Fsym = (H + H^T)/2 + couMat  (couMat already symmetric)
    for (int i = tid; i < 4096; i += 256) {
        int r = i >> 6, c = i & 63;
        b2[r * 65 + c] = 0.5f * (Hg[i] + Hg[c * 64 + r])
                       - 0.5f * b1[r * 65 + c] * (sep[r] + sep[c]);
    }
    __syncthreads();
    int tx = tid & 15, ty = tid >> 4, r0 = ty * 4, c0 = tx * 4;
    float acc[4][4];
#pragma unroll
    for (int i = 0; i < 4; i++)
#pragma unroll
        for (int j = 0; j < 4; j++) acc[i][j] = 0.0f;
    for (int k = 0; k < 64; k++) {
        float a0 = b2[(r0 + 0) * 65 + k], a1 = b2[(r0 + 1) * 65 + k];
        float a2 = b2[(r0 + 2) * 65 + k], a3 = b2[(r0 + 3) * 65 + k];
        float q0 = b3[k * 65 + c0], q1 = b3[k * 65 + c0 + 1];
        float q2 = b3[k * 65 + c0 + 2], q3 = b3[k * 65 + c0 + 3];
        acc[0][0] += a0 * q0; acc[0][1] += a0 * q1; acc[0][2] += a0 * q2; acc[0][3] += a0 * q3;
        acc[1][0] += a1 * q0; acc[1][1] += a1 * q1; acc[1][2] += a1 * q2; acc[1][3] += a1 * q3;
        acc[2][0] += a2 * q0; acc[2][1] += a2 * q1; acc[2][2] += a2 * q2; acc[2][3] += a2 * q3;
        acc[3][0] += a3 * q0; acc[3][1] += a3 * q1; acc[3][2] += a3 * q2; acc[3][3] += a3 * q3;
    }
    __syncthreads();
#pragma unroll
    for (int i = 0; i < 4; i++)
#pragma unroll
        for (int j = 0; j < 4; j++) b1[(r0 + i) * 65 + c0 + j] = acc[i][j];
    __syncthreads();
#pragma unroll
    for (int i = 0; i < 4; i++)
#pragma unroll
        for (int j = 0; j < 4; j++) acc[i][j] = 0.0f;
    for (int k = 0; k < 64; k++) {
        float a0 = b3[k * 65 + r0 + 0], a1 = b3[k * 65 + r0 + 1];
        float a2 = b3[k * 65 + r0 + 2], a3 = b3[k * 65 + r0 + 3];
        float q0 = b1[k * 65 + c0], q1 = b1[k * 65 + c0 + 1];
        float q2 = b1[k * 65 + c0 + 2], q3 = b1[k * 65 + c0 + 3];
        acc[0][0] += a0 * q0; acc[0][1] += a0 * q1; acc[0][2] += a0 * q2; acc[0][3] += a0 * q3;
        acc[1][0] += a1 * q0; acc[1][1] += a1 * q1; acc[1][2] += a1 * q2; acc[1][3] += a1 * q3;
        acc[2][0] += a2 * q0; acc[2][1] += a2 * q1; acc[2][2] += a2 * q2; acc[2][3] += a2 * q3;
        acc[3][0] += a3 * q0; acc[3][1] += a3 * q1; acc[3][2] += a3 * q2; acc[3][3] += a3 * q3;
    }
    float* fo = g_fockp + (size_t)g * 4096;
#pragma unroll
    for (int i = 0; i < 4; i++)
#pragma unroll
        for (int j = 0; j < 4; j++) fo[(r0 + i) * 64 + c0 + j] = acc[i][j];
}

// ---------------- Kernel 4: Erep ----------------
__global__ void k_erep(const float* __restrict__ net, const int* __restrict__ gr,
                       const int* __restrict__ seg, float* __restrict__ out_erep) {
    __shared__ int sbnd[2];
    __shared__ float sred[256];
    int g = blockIdx.x, tid = threadIdx.x;
    if (tid < 2) {
        int target = g + tid, lo = 0, hi = EREPN;
        while (lo < hi) {
            int mid = (lo + hi) >> 1;
            if (seg[mid] < target) lo = mid + 1; else hi = mid;
        }
        sbnd[tid] = lo;
    }
    __syncthreads();
    float s = 0.0f;
    for (int i = sbnd[0] + tid; i < sbnd[1]; i += 256) s += net[gr[i]];
    sred[tid] = s;
    __syncthreads();
    for (int o = 128; o; o >>= 1) {
        if (tid < o) sred[tid] += sred[tid + o];
        __syncthreads();
    }
    if (!tid) out_erep[g] = sred[0];
}

// ---------------- Kernel 5: Brent-Luk Jacobi ----------------
__global__ void __launch_bounds__(256, 4) k_jac(float* __restrict__ out) {
    extern __shared__ float sm[];           // 4160 floats: staging / exchange
    __shared__ float sc[32], ss[32], sd[64], sred[256], sfrob;
    __shared__ int sflag;
    int g = blockIdx.x, tid = threadIdx.x;
    int w = tid >> 5, l = tid & 31;
    const float* fp = g_fockp + (size_t)g * 4096;

    // stage fockp (already symmetric)
    for (int i = tid; i < 4096; i += 256) {
        int r = i >> 6, c = i & 63;
        sm[r * 65 + c] = fp[i];
    }
    __syncthreads();

    float A0[8], A1[8], V0[8], V1[8];
    float fl = 0.0f;
#pragma unroll
    for (int j = 0; j < 8; j++) {
        int cg = 8 * w + j;
        A0[j] = sm[(2 * l) * 65 + cg];
        A1[j] = sm[(2 * l + 1) * 65 + cg];
        fl += A0[j] * A0[j] + A1[j] * A1[j];
        V0[j] = (2 * l == cg) ? 1.0f : 0.0f;
        V1[j] = (2 * l + 1 == cg) ? 1.0f : 0.0f;
    }
    sred[tid] = fl;
    __syncthreads();
    for (int o = 128; o; o >>= 1) {
        if (tid < o) sred[tid] += sred[tid + o];
        __syncthreads();
    }
    if (!tid) { sfrob = sred[0]; sflag = 0; }
    __syncthreads();

    float2* xb = (float2*)sm;

    for (int sweep = 0; sweep < 16; sweep++) {
#pragma unroll 3
        for (int rnd = 0; rnd < 63; rnd++) {
            if ((l >> 2) == w) {
                int j = l & 3;
                float app = A0[2 * j], aqq = A1[2 * j + 1], apq = A0[2 * j + 1];
                float c, s;
                if (fabsf(apq) < 1e-30f) { c = 1.0f; s = 0.0f; }
                else {
                    float tau = (aqq - app) / (2.0f * apq);
                    float t = copysignf(1.0f / (fabsf(tau) + sqrtf(1.0f + tau * tau)), tau);
                    c = rsqrtf(1.0f + t * t);
                    s = t * c;
                }
                sc[l] = c; ss[l] = s;
            }
            __syncthreads();
            float cr = sc[l], sr = ss[l];
            // right rotation on column pairs
#pragma unroll
            for (int jj = 0; jj < 4; jj++) {
                float cc = sc[4 * w + jj], s2 = ss[4 * w + jj];
                int a = 2 * jj, b = a + 1;
                float x, y;
                x = A0[a]; y = A0[b]; A0[a] = cc * x - s2 * y; A0[b] = s2 * x + cc * y;
                x = A1[a]; y = A1[b]; A1[a] = cc * x - s2 * y; A1[b] = s2 * x + cc * y;
                x = V0[a]; y = V0[b]; V0[a] = cc * x - s2 * y; V0[b] = s2 * x + cc * y;
                x = V1[a]; y = V1[b]; V1[a] = cc * x - s2 * y; V1[b] = s2 * x + cc * y;
            }
            // left rotation + row migration (2 shuffles per column)
#pragma unroll
            for (int j = 0; j < 8; j++) {
                float x = A0[j], y = A1[j];
                float r0 = cr * x - sr * y;
                float r1 = sr * x + cr * y;
                float tmp = (l == 0) ? r1 : r0;
                float up = __shfl_up_sync(0xffffffffu, tmp, 1);
                float dn = __shfl_down_sync(0xffffffffu, r1, 1);
                A0[j] = (l == 0) ? r0 : up;
                A1[j] = (l == 31) ? r0 : dn;
            }
            // stage boundary columns
            xb[(w * 4 + 0) * 32 + l] = make_float2(A0[6], A1[6]);
            xb[(w * 4 + 1) * 32 + l] = make_float2(A0[1], A1[1]);
            xb[(w * 4 + 2) * 32 + l] = make_float2(V0[6], V1[6]);
            xb[(w * 4 + 3) * 32 + l] = make_float2(V0[1], V1[1]);
            __syncthreads();
            // column migration (MOVs vanish under unroll via copy-prop)
            {
                float a1_0 = A0[1], a1_1 = A1[1], a6_0 = A0[6], a6_1 = A1[6];
                float v1_0 = V0[1], v1_1 = V1[1], v6_0 = V0[6], v6_1 = V1[6];
                A0[6] = A0[4]; A1[6] = A1[4]; A0[4] = A0[2]; A1[4] = A1[2];
                V0[6] = V0[4]; V1[6] = V1[4]; V0[4] = V0[2]; V1[4] = V1[2];
                if (w == 0) { A0[2] = a1_0; A1[2] = a1_1; V0[2] = v1_0; V1[2] = v1_1; }
                else        { A0[2] = A0[0]; A1[2] = A1[0]; V0[2] = V0[0]; V1[2] = V1[0]; }
                if (w > 0) {
                    float2 ra = xb[((w - 1) * 4 + 0) * 32 + l];
                    float2 rv = xb[((w - 1) * 4 + 2) * 32 + l];
                    A0[0] = ra.x; A1[0] = ra.y; V0[0] = rv.x; V1[0] = rv.y;
                }
                A0[1] = A0[3]; A1[1] = A1[3]; A0[3] = A0[5]; A1[3] = A1[5];
                A0[5] = A0[7]; A1[5] = A1[7];
                V0[1] = V0[3]; V1[1] = V1[3]; V0[3] = V0[5]; V1[3] = V1[5];
                V0[5] = V0[7]; V1[5] = V1[7];
                if (w == 7) { A0[7] = a6_0; A1[7] = a6_1; V0[7] = v6_0; V1[7] = v6_1; }
                else {
                    float2 ra = xb[((w + 1) * 4 + 1) * 32 + l];
                    float2 rv = xb[((w + 1) * 4 + 3) * 32 + l];
                    A0[7] = ra.x; A1[7] = ra.y; V0[7] = rv.x; V1[7] = rv.y;
                }
            }
        }
        if (sweep < 3) continue;   // never converges this early
        // sweep-end convergence check (identity order)
        float off = 0.0f;
#pragma unroll
        for (int j = 0; j < 8; j++) {
            int cg = 8 * w + j;
            if (2 * l != cg)     off += A0[j] * A0[j];
            if (2 * l + 1 != cg) off += A1[j] * A1[j];
        }
        sred[tid] = off;
        __syncthreads();
        for (int o = 128; o; o >>= 1) {
            if (tid < o) sred[tid] += sred[tid + o];
            __syncthreads();
        }
        if (!tid && sred[0] <= 1e-10f * sfrob) sflag = 1;
        __syncthreads();
        if (sflag) break;
    }

    // dump V to shared staging, extract eigenvalues
    __syncthreads();
#pragma unroll
    for (int j = 0; j < 8; j++) {
        int cg = 8 * w + j;
        sm[(2 * l) * 65 + cg] = V0[j];
        sm[(2 * l + 1) * 65 + cg] = V1[j];
        if (2 * l == cg)     sd[cg] = A0[j];
        if (2 * l + 1 == cg) sd[cg] = A1[j];
    }
    __syncthreads();
    float* Vg = g_V + (size_t)g * 4096;
    for (int i = tid; i < 4096; i += 256) {
        int r = i >> 6, c = i & 63;
        Vg[i] = sm[r * 65 + c];
    }
    if (tid < 64) {
        float d = sd[tid];
        int r = 0;
        for (int jj = 0; jj < 64; jj++)
            r += (sd[jj] < d) || (sd[jj] == d && jj < tid);
        g_perm[g * 64 + r] = tid;
        out[OFF_EORB + g * 64 + r] = d;
    }
}

// ---------------- Kernel 5b: post-eig GEMMs + rho_out + energies -----------
__global__ void k_post(const float* __restrict__ phiS, const float* __restrict__ occ,
                       const float* __restrict__ outH, float* __restrict__ out) {
    extern __shared__ float sm[];
    float* b1 = sm;          // orb_filled
    float* b2 = sm + 4160;   // V
    float* b3 = sm + 8320;   // phiS
    __shared__ float sred[256];
    __shared__ int scol[64];
    int g = blockIdx.x, tid = threadIdx.x;
    const float* Vg = g_V + (size_t)g * 4096;
    const float* Pg = phiS + (size_t)g * 4096;
    for (int i = tid; i < 4096; i += 256) {
        int r = i >> 6, c = i & 63;
        b2[r * 65 + c] = Vg[i];
        b3[r * 65 + c] = Pg[i];
    }
    if (tid < 64) scol[tid] = g_perm[g * 64 + tid];
    __syncthreads();

    int tx = tid & 15, ty = tid >> 4, r0 = ty * 4, c0 = tx * 4;
    const float* Og = occ + (size_t)g * 4096;
    const float* Hg = outH + (size_t)g * 4096;
    float acc[4][4];
    int j0 = scol[c0], j1 = scol[c0 + 1], j2 = scol[c0 + 2], j3 = scol[c0 + 3];
#pragma unroll
    for (int i = 0; i < 4; i++)
#pragma unroll
        for (int j = 0; j < 4; j++) acc[i][j] = 0.0f;
    for (int k = 0; k < 64; k++) {
        float a0 = b3[(r0 + 0) * 65 + k], a1 = b3[(r0 + 1) * 65 + k];
        float a2 = b3[(r0 + 2) * 65 + k], a3 = b3[(r0 + 3) * 65 + k];
        float q0 = b2[k * 65 + j0], q1 = b2[k * 65 + j1];
        float q2 = b2[k * 65 + j2], q3 = b2[k * 65 + j3];
        acc[0][0] += a0 * q0; acc[0][1] += a0 * q1; acc[0][2] += a0 * q2; acc[0][3] += a0 * q3;
        acc[1][0] += a1 * q0; acc[1][1] += a1 * q1; acc[1][2] += a1 * q2; acc[1][3] += a1 * q3;
        acc[2][0] += a2 * q0; acc[2][1] += a2 * q1; acc[2][2] += a2 * q2; acc[2][3] += a2 * q3;
        acc[3][0] += a3 * q0; acc[3][1] += a3 * q1; acc[3][2] += a3 * q2; acc[3][3] += a3 * q3;
    }
#pragma unroll
    for (int i = 0; i < 4; i++)
#pragma unroll
        for (int j = 0; j < 4; j++)
            b1[(r0 + i) * 65 + c0 + j] = Og[(r0 + i) * 64 + c0 + j] * acc[i][j];
    __syncthreads();
#pragma unroll
    for (int i = 0; i < 4; i++)
#pragma unroll
        for (int j = 0; j < 4; j++) acc[i][j] = 0.0f;
    for (int k = 0; k < 64; k++) {
        float a0 = b1[(r0 + 0) * 65 + k], a1 = b1[(r0 + 1) * 65 + k];
        float a2 = b1[(r0 + 2) * 65 + k], a3 = b1[(r0 + 3) * 65 + k];
        float q0 = b1[(c0 + 0) * 65 + k], q1 = b1[(c0 + 1) * 65 + k];
        float q2 = b1[(c0 + 2) * 65 + k], q3 = b1[(c0 + 3) * 65 + k];
        acc[0][0] += a0 * q0; acc[0][1] += a0 * q1; acc[0][2] += a0 * q2; acc[0][3] += a0 * q3;
        acc[1][0] += a1 * q0; acc[1][1] += a1 * q1; acc[1][2] += a1 * q2; acc[1][3] += a1 * q3;
        acc[2][0] += a2 * q0; acc[2][1] += a2 * q1; acc[2][2] += a2 * q2; acc[2][3] += a2 * q3;
        acc[3][0] += a3 * q0; acc[3][1] += a3 * q1; acc[3][2] += a3 * q2; acc[3][3] += a3 * q3;
    }
    float* Ro = out + OFF_RHO + (size_t)g * 4096;
    float e1 = 0.0f;
#pragma unroll
    for (int i = 0; i < 4; i++)
#pragma unroll
        for (int j = 0; j < 4; j++) {
            float v = 2.0f * acc[i][j];
            Ro[(r0 + i) * 64 + c0 + j] = v;
            e1 += v * Hg[(r0 + i) * 64 + c0 + j];
        }
    sred[tid] = e1;
    __syncthreads();
    for (int o = 128; o; o >>= 1) {
        if (tid < o) sred[tid] += sred[tid + o];
        __syncthreads();
    }
    if (!tid) out[OFF_EELEC + g] = sred[0] + g_ener2[g];
}

// ---------------- Kernel 6: Eref ----------------
__global__ void k_eref(const float* __restrict__ zc, const float* __restrict__ rv,
                       float* __restrict__ out) {
    if (threadIdx.x == 0) {
        float s = 0.0f;
        for (int i = 0; i < 7; i++) s += zc[i] * rv[i];
        out[OFF_EREF] = s;
    }
}

extern "C" void kernel_launch(void* const* d_in, const int* in_sizes, int n_in,
                              void* d_out, int out_size) {
    const float* net   = (const float*)d_in[0];
    const float* rotT  = (const float*)d_in[1];
    const float* S     = (const float*)d_in[2];
    const float* G     = (const float*)d_in[3];
    const float* rho   = (const float*)d_in[4];
    const float* qn    = (const float*)d_in[5];
    const float* occ   = (const float*)d_in[6];
    const float* phiS  = (const float*)d_in[7];
    const float* zc    = (const float*)d_in[8];
    const float* rv    = (const float*)d_in[9];
    const int* grot    = (const int*)d_in[10];
    const int* goper   = (const int*)d_in[11];
    const int* grep    = (const int*)d_in[12];
    const int* segrep  = (const int*)d_in[13];
    float* out = (float*)d_out;

    static bool attr_done = false;
    if (!attr_done) {
        cudaFuncSetAttribute(k_pre, cudaFuncAttributeMaxDynamicSharedMemorySize, 49920);
        cudaFuncSetAttribute(k_post, cudaFuncAttributeMaxDynamicSharedMemorySize, 49920);
        attr_done = true;
    }

    k_rot<<<(RROT + 255) / 256, 256>>>(net, rotT, grot);
    k_hgather<<<NGBB / 4 / 256, 256>>>(goper, out + OFF_H);
    k_pre<<<NGEO, 256, 49920>>>(S, G, rho, qn, phiS, out + OFF_H, out + OFF_DQ);
    k_jac<<<NGEO, 256, 16640>>>(out);        // 4th launch — the profiled slot
    k_erep<<<NGEO, 256>>>(net, grep, segrep, out + OFF_EREP);
    k_post<<<NGEO, 256, 49920>>>(phiS, occ, out + OFF_H, out);
    k_eref<<<1, 32>>>(zc, rv, out);
}